// round 12
// baseline (speedup 1.0000x reference)
#include <cuda_runtime.h>
#include <cuda_fp16.h>
#include <cstdint>

#define BB   64
#define TT   200
#define INF  512
#define HID  1024
#define OUTF 512
#define DELAYS 20
#define BH   (BB * HID)          // 65536
#define NBLK (TT / DELAYS)       // 10
#define MBLK (DELAYS * BB)       // 1280
#define STG  3

// ---------------- scratch (device globals) ----------------------------------
__device__ __half g_xh[(size_t)TT * BB * INF];
__device__ __half g_Win[(size_t)INF * HID];
__device__ __half g_Wlat[(size_t)HID * HID];
__device__ __half g_WoutT[(size_t)HID * OUTF];
__device__ float  g_syn[(size_t)TT * BH];
__device__ __half g_firing[(size_t)TT * BH];
__device__ float  g_volt[BH];
__device__ float  g_asc[2 * BH];
__device__ float  g_fire[BH];

// ---------------- streams / events -------------------------------------------
struct Ctx {
    cudaStream_t s1, s2;
    cudaEvent_t e_fork, e_win, e_wlat, e_trans;
    Ctx() {
        cudaStreamCreateWithFlags(&s1, cudaStreamNonBlocking);
        cudaStreamCreateWithFlags(&s2, cudaStreamNonBlocking);
        cudaEventCreateWithFlags(&e_fork,  cudaEventDisableTiming);
        cudaEventCreateWithFlags(&e_win,   cudaEventDisableTiming);
        cudaEventCreateWithFlags(&e_wlat,  cudaEventDisableTiming);
        cudaEventCreateWithFlags(&e_trans, cudaEventDisableTiming);
    }
};
static Ctx g_ctx;

// ---------------- PDL helpers -------------------------------------------------
__device__ __forceinline__ void gdc_launch() {
    asm volatile("griddepcontrol.launch_dependents;");
}
__device__ __forceinline__ void gdc_wait() {
    asm volatile("griddepcontrol.wait;" ::: "memory");
}

template<typename F, typename... Args>
static void pdl_launch(F* f, dim3 g, dim3 b, size_t sm, cudaStream_t st, Args... args) {
    cudaLaunchConfig_t cfg = {};
    cfg.gridDim = g; cfg.blockDim = b;
    cfg.dynamicSmemBytes = sm; cfg.stream = st;
    cudaLaunchAttribute at[1];
    at[0].id = cudaLaunchAttributeProgrammaticStreamSerialization;
    at[0].val.programmaticStreamSerializationAllowed = 1;
    cfg.attrs = at; cfg.numAttrs = 1;
    cudaLaunchKernelEx(&cfg, f, args...);
}

// ---------------- PTX helpers ------------------------------------------------
__device__ __forceinline__ void cp16(void* dst, const void* src) {
    uint32_t d = (uint32_t)__cvta_generic_to_shared(dst);
    asm volatile("cp.async.cg.shared.global [%0], [%1], 16;\n" :: "r"(d), "l"(src));
}
__device__ __forceinline__ void cp_commit() { asm volatile("cp.async.commit_group;\n"); }
__device__ __forceinline__ void cp_wait1()  { asm volatile("cp.async.wait_group 1;\n"); }

__device__ __forceinline__ void ldmx4(uint32_t* r, uint32_t addr) {
    asm volatile("ldmatrix.sync.aligned.m8n8.x4.shared.b16 {%0,%1,%2,%3}, [%4];\n"
                 : "=r"(r[0]), "=r"(r[1]), "=r"(r[2]), "=r"(r[3]) : "r"(addr));
}
__device__ __forceinline__ void ldmx4t(uint32_t* r, uint32_t addr) {
    asm volatile("ldmatrix.sync.aligned.m8n8.x4.trans.shared.b16 {%0,%1,%2,%3}, [%4];\n"
                 : "=r"(r[0]), "=r"(r[1]), "=r"(r[2]), "=r"(r[3]) : "r"(addr));
}
__device__ __forceinline__ void mma16816(float* c, const uint32_t* a, const uint32_t* b) {
    asm volatile(
        "mma.sync.aligned.m16n8k16.row.col.f32.f16.f16.f32 "
        "{%0,%1,%2,%3}, {%4,%5,%6,%7}, {%8,%9}, {%0,%1,%2,%3};\n"
        : "+f"(c[0]), "+f"(c[1]), "+f"(c[2]), "+f"(c[3])
        : "r"(a[0]), "r"(a[1]), "r"(a[2]), "r"(a[3]), "r"(b[0]), "r"(b[1]));
}

// ---------------- mma.sync GEMM (champion config + PDL) -----------------------
// BK = 64 halves, SW128 xor swizzle, 3-stage cp.async pipeline
// MODE 0: plain store   1: C += acc   2: bias + permuted store to [B][T][OUT]
// PDL safety: nothing before gdc_wait touches chain-written memory.
template<int BM, int BN, int WM, int WN, int MODE>
__global__ __launch_bounds__(WM * WN * 32, MODE == 1 ? 4 : 2) void mgemm(
    const __half* __restrict__ A, const __half* __restrict__ Bm,
    float* __restrict__ C, const float* __restrict__ bias,
    int M, int N, int K)
{
    constexpr int THREADS = WM * WN * 32;
    constexpr int RPW = BM / WM;
    constexpr int CPW = BN / WN;
    constexpr int MF  = RPW / 16;
    constexpr int NF  = CPW / 8;

    extern __shared__ __half smem[];
    __half* sA = smem;                    // [STG][BM*64]
    __half* sB = smem + STG * BM * 64;    // [STG][64*BN]

    gdc_launch();

    const int tid  = threadIdx.x;
    const int l    = tid & 31;
    const int warp = tid >> 5;
    const int wm   = (warp / WN) * RPW;
    const int wn   = (warp % WN) * CPW;
    const int bm   = blockIdx.y * BM;
    const int bn   = blockIdx.x * BN;

    float acc[MF][NF][4] = {};
    const int KT = K >> 6;

    auto load_stage = [&](int kt, int st) {
        const int k0 = kt << 6;
        constexpr int GA = BM * 8 / THREADS;
#pragma unroll
        for (int i = 0; i < GA; i++) {
            int c = tid + i * THREADS;
            int row = c >> 3, g = c & 7;
            cp16(sA + st * BM * 64 + row * 64 + ((g ^ (row & 7)) << 3),
                 A + (size_t)(bm + row) * K + k0 + (g << 3));
        }
        constexpr int GB = 8 * BN / THREADS;
#pragma unroll
        for (int i = 0; i < GB; i++) {
            int c = tid + i * THREADS;
            int k = c / (BN / 8), g = c % (BN / 8);
            int blk = g >> 3, gg = (g & 7) ^ (k & 7);
            cp16(sB + st * 64 * BN + k * BN + blk * 64 + (gg << 3),
                 Bm + (size_t)(k0 + k) * N + bn + (g << 3));
        }
    };

    // all predecessor-written data (A, and C for MODE 1) read only after this
    gdc_wait();

    load_stage(0, 0); cp_commit();
    load_stage(1, 1); cp_commit();

    for (int kt = 0; kt < KT; kt++) {
        const int st = kt % STG;
        cp_wait1();
        __syncthreads();
        if (kt + 2 < KT) load_stage(kt + 2, (kt + 2) % STG);
        cp_commit();

        uint32_t baseA = (uint32_t)__cvta_generic_to_shared(sA + st * BM * 64);
        uint32_t baseB = (uint32_t)__cvta_generic_to_shared(sB + st * 64 * BN);

#pragma unroll
        for (int kk = 0; kk < 4; kk++) {
            uint32_t a[MF][4];
#pragma unroll
            for (int i = 0; i < MF; i++) {
                int row = wm + i * 16 + (l & 15);
                int g   = kk * 2 + (l >> 4);
                ldmx4(a[i], baseA + (uint32_t)(row * 64 + ((g ^ (row & 7)) << 3)) * 2);
            }
            uint32_t b[NF / 2][4];
#pragma unroll
            for (int j = 0; j < NF / 2; j++) {
                int k = kk * 16 + (l & 15);
                int g = ((wn + j * 16) >> 3) + (l >> 4);
                int blk = g >> 3, gg = (g & 7) ^ (k & 7);
                ldmx4t(b[j], baseB + (uint32_t)(k * BN + blk * 64 + (gg << 3)) * 2);
            }
#pragma unroll
            for (int i = 0; i < MF; i++)
#pragma unroll
                for (int j = 0; j < NF / 2; j++) {
                    mma16816(acc[i][2 * j],     a[i], b[j]);
                    mma16816(acc[i][2 * j + 1], a[i], b[j] + 2);
                }
        }
    }

    // ---- epilogue ----
    const int r  = l >> 2;
    const int c0 = (l & 3) * 2;
#pragma unroll
    for (int i = 0; i < MF; i++) {
        int m0 = bm + wm + i * 16;
#pragma unroll
        for (int j = 0; j < NF; j++) {
            int col = bn + wn + j * 8 + c0;
#pragma unroll
            for (int h = 0; h < 2; h++) {
                int m = m0 + r + h * 8;
                float2 val = make_float2(acc[i][j][2 * h], acc[i][j][2 * h + 1]);
                if (MODE == 0) {
                    *reinterpret_cast<float2*>(&C[(size_t)m * N + col]) = val;
                } else if (MODE == 1) {
                    float2* p = reinterpret_cast<float2*>(&C[(size_t)m * N + col]);
                    float2 o = *p;
                    o.x += val.x; o.y += val.y;
                    *p = o;
                } else {
                    float2 bb = *reinterpret_cast<const float2*>(&bias[col]);
                    val.x += bb.x; val.y += bb.y;
                    int t = m >> 6, b0 = m & 63;
                    *reinterpret_cast<float2*>(
                        &C[((size_t)b0 * TT + t) * OUTF + col]) = val;
                }
            }
        }
    }
}

// ---------------- conversion kernels -----------------------------------------
__global__ __launch_bounds__(256) void convx_kernel(const float* __restrict__ x,
                                                    __half* __restrict__ xh)
{
    gdc_launch();
    int i  = blockIdx.x * 256 + threadIdx.x;
    int i4 = i % (INF / 4);
    int bt = i / (INF / 4);
    int b = bt / TT, t = bt % TT;
    float4 v = reinterpret_cast<const float4*>(x)[i];
    int dst = (t * BB + b) * (INF / 4) + i4;
    reinterpret_cast<__half2*>(xh)[2 * dst + 0] = __floats2half2_rn(v.x, v.y);
    reinterpret_cast<__half2*>(xh)[2 * dst + 1] = __floats2half2_rn(v.z, v.w);
}

__global__ __launch_bounds__(256) void f2h_kernel(const float* __restrict__ in,
                                                  __half* __restrict__ out)
{
    int i = blockIdx.x * 256 + threadIdx.x;
    float4 v = reinterpret_cast<const float4*>(in)[i];
    reinterpret_cast<__half2*>(out)[2 * i + 0] = __floats2half2_rn(v.x, v.y);
    reinterpret_cast<__half2*>(out)[2 * i + 1] = __floats2half2_rn(v.z, v.w);
}

__global__ void transp_kernel(const float* __restrict__ w, __half* __restrict__ wt)
{
    __shared__ float tile[32][33];
    int ox = blockIdx.x * 32, hy = blockIdx.y * 32;
    int tx = threadIdx.x, ty = threadIdx.y;
#pragma unroll
    for (int rr = 0; rr < 32; rr += 8)
        tile[ty + rr][tx] = w[(size_t)(ox + ty + rr) * HID + hy + tx];
    __syncthreads();
#pragma unroll
    for (int rr = 0; rr < 32; rr += 8)
        wt[(size_t)(hy + ty + rr) * OUTF + ox + tx] = __float2half(tile[tx][ty + rr]);
}

// ---------------- elementwise 20-step scan (PDL, race-free) -------------------
__device__ __forceinline__ float sigm(float x) { return 1.0f / (1.0f + __expf(-x)); }

__global__ __launch_bounds__(256) void scan_kernel(
    const float* __restrict__ syn_all,
    const float* __restrict__ trans_k_m,
    const float* __restrict__ trans_asc_k,
    const float* __restrict__ asc_amp,
    const float* __restrict__ trans_asc_r,
    const float* __restrict__ thresh,
    __half* __restrict__ firing,
    float* __restrict__ volt_st, float* __restrict__ asc_st,
    float* __restrict__ fire_st, int t0)
{
    gdc_launch();

    int idx = blockIdx.x * blockDim.x + threadIdx.x;
    int h = idx & (HID - 1);

    // ---- pre-wait: ONLY kernel-input constants (never written by the chain) --
    float km  = sigm(trans_k_m[h]);
    float c1  = 0.1f * km;
    float c2  = 1.0f - km;
    float ka0 = sigm(trans_asc_k[h]);
    float ka1 = sigm(trans_asc_k[HID + h]);
    float amp0 = asc_amp[h],       amp1 = asc_amp[HID + h];
    float r0 = 1.0f - 2.0f * sigm(trans_asc_r[h]);
    float r1 = 1.0f - 2.0f * sigm(trans_asc_r[HID + h]);
    float th = thresh[h];

    // ---- wait: predecessor (lateral GEMM) complete => prior scan complete ----
    gdc_wait();

    float f, v, a0, a1;
    if (t0 == 0) {
        f = 0.f; v = 0.f; a0 = 0.f; a1 = 0.f;
    } else {
        f  = fire_st[idx];
        v  = volt_st[idx];
        a0 = asc_st[idx];
        a1 = asc_st[BH + idx];
    }

    float syn[DELAYS];
#pragma unroll
    for (int s = 0; s < DELAYS; s++)
        syn[s] = syn_all[(size_t)(t0 + s) * BH + idx];

#pragma unroll
    for (int s = 0; s < DELAYS; s++) {
        a0 = (amp0 + r0 * a0) * f * ka0 + (1.0f - ka0) * a0;
        a1 = (amp1 + r1 * a1) * f * ka1 + (1.0f - ka1) * a1;
        v  = c1 * (syn[s] + a0 + a1) + c2 * v;
        f  = sigm(v - th);
        firing[(size_t)(t0 + s) * BH + idx] = __float2half(f);
    }
    fire_st[idx] = f;
    volt_st[idx] = v;
    asc_st[idx] = a0;
    asc_st[BH + idx] = a1;
}

// ---------------- launch ------------------------------------------------------
extern "C" void kernel_launch(void* const* d_in, const int* in_sizes, int n_in,
                              void* d_out, int out_size)
{
    const float* x           = (const float*)d_in[0];
    const float* W_in        = (const float*)d_in[1];
    const float* W_lat       = (const float*)d_in[2];
    const float* thresh      = (const float*)d_in[3];
    const float* trans_k_m   = (const float*)d_in[4];
    const float* trans_asc_k = (const float*)d_in[5];
    const float* asc_amp     = (const float*)d_in[6];
    const float* trans_asc_r = (const float*)d_in[7];
    const float* W_out       = (const float*)d_in[8];
    const float* b_out       = (const float*)d_in[9];
    float* out = (float*)d_out;

    __half *xh, *Win, *Wlat, *WoutT, *firing;
    float *syn, *volt, *asc, *fire;
    cudaGetSymbolAddress((void**)&xh,     g_xh);
    cudaGetSymbolAddress((void**)&Win,    g_Win);
    cudaGetSymbolAddress((void**)&Wlat,   g_Wlat);
    cudaGetSymbolAddress((void**)&WoutT,  g_WoutT);
    cudaGetSymbolAddress((void**)&syn,    g_syn);
    cudaGetSymbolAddress((void**)&firing, g_firing);
    cudaGetSymbolAddress((void**)&volt,   g_volt);
    cudaGetSymbolAddress((void**)&asc,    g_asc);
    cudaGetSymbolAddress((void**)&fire,   g_fire);

    const int SM_BIG = STG * (128 * 64 + 64 * 128) * 2;   // 98304
    const int SM_LAT = STG * (64 * 64 + 64 * 64) * 2;     // 49152
    cudaFuncSetAttribute(mgemm<128, 128, 4, 2, 0>,
                         cudaFuncAttributeMaxDynamicSharedMemorySize, SM_BIG);
    cudaFuncSetAttribute(mgemm<64, 64, 2, 2, 1>,
                         cudaFuncAttributeMaxDynamicSharedMemorySize, SM_LAT);
    cudaFuncSetAttribute(mgemm<128, 128, 4, 2, 2>,
                         cudaFuncAttributeMaxDynamicSharedMemorySize, SM_BIG);

    cudaStream_t s0 = 0, s1 = g_ctx.s1, s2 = g_ctx.s2;

    // ---- fork event FIRST (capture-legal fork of side streams) ----
    cudaEventRecord(g_ctx.e_fork, s0);

    // ---- s1: weight fp16 conversions ----
    cudaStreamWaitEvent(s1, g_ctx.e_fork, 0);
    f2h_kernel<<<(INF * HID / 4) / 256, 256, 0, s1>>>(W_in, Win);
    cudaEventRecord(g_ctx.e_win, s1);
    f2h_kernel<<<(HID * HID / 4) / 256, 256, 0, s1>>>(W_lat, Wlat);
    cudaEventRecord(g_ctx.e_wlat, s1);

    // ---- s2: W_out transpose ----
    cudaStreamWaitEvent(s2, g_ctx.e_fork, 0);
    transp_kernel<<<dim3(OUTF / 32, HID / 32), dim3(32, 8), 0, s2>>>(W_out, WoutT);
    cudaEventRecord(g_ctx.e_trans, s2);

    // ---- main stream: champion schedule, all links PDL ----
    pdl_launch(convx_kernel, dim3((BB * TT * INF / 4) / 256), dim3(256),
               (size_t)0, s0, x, xh);
    cudaStreamWaitEvent(s0, g_ctx.e_win, 0);
    pdl_launch(mgemm<128, 128, 4, 2, 0>,
               dim3(HID / 128, (BB * TT) / 128), dim3(256), (size_t)SM_BIG, s0,
               (const __half*)xh, (const __half*)Win, syn, (const float*)nullptr,
               BB * TT, HID, INF);
    cudaStreamWaitEvent(s0, g_ctx.e_wlat, 0);

    for (int blk = 0; blk < NBLK; blk++) {
        if (blk > 0) {
            pdl_launch(mgemm<64, 64, 2, 2, 1>,
                       dim3(HID / 64, MBLK / 64), dim3(128), (size_t)SM_LAT, s0,
                       (const __half*)(firing + (size_t)(blk - 1) * MBLK * HID),
                       (const __half*)Wlat,
                       syn + (size_t)blk * MBLK * HID, (const float*)nullptr,
                       MBLK, HID, HID);
        }
        pdl_launch(scan_kernel, dim3(BH / 256), dim3(256), (size_t)0, s0,
                   (const float*)syn, trans_k_m, trans_asc_k, asc_amp,
                   trans_asc_r, thresh, (__half*)firing, volt, asc, fire,
                   blk * DELAYS);
    }

    // ---- readout: single full GEMM with fused bias + permute ----
    cudaStreamWaitEvent(s0, g_ctx.e_trans, 0);
    pdl_launch(mgemm<128, 128, 4, 2, 2>,
               dim3(OUTF / 128, (BB * TT) / 128), dim3(256), (size_t)SM_BIG, s0,
               (const __half*)firing, (const __half*)WoutT, out, b_out,
               BB * TT, OUTF, HID);
}

// round 13
// speedup vs baseline: 1.0131x; 1.0131x over previous
#include <cuda_runtime.h>
#include <cuda_fp16.h>
#include <cstdint>

#define BB   64
#define TT   200
#define INF  512
#define HID  1024
#define OUTF 512
#define DELAYS 20
#define BH   (BB * HID)          // 65536
#define NBLK (TT / DELAYS)       // 10
#define MBLK (DELAYS * BB)       // 1280
#define STG  3
#define LAT_CTAS 320             // (HID/64) * (MBLK/64) = 16 * 20
#define SCAN_THREADS (LAT_CTAS * 128)   // 40960

// ---------------- scratch (device globals) ----------------------------------
__device__ __half g_xh[(size_t)TT * BB * INF];
__device__ __half g_Win[(size_t)INF * HID];
__device__ __half g_Wlat[(size_t)HID * HID];
__device__ __half g_WoutT[(size_t)HID * OUTF];
__device__ float  g_syn[(size_t)TT * BH];
__device__ __half g_firing[(size_t)TT * BH];
__device__ float  g_volt[BH];
__device__ float  g_asc[2 * BH];
__device__ float  g_fire[BH];
__device__ int    g_ctr[NBLK];          // arrival counters, zeroed by convx

// ---------------- streams / events -------------------------------------------
struct Ctx {
    cudaStream_t s1, s2;
    cudaEvent_t e_fork, e_win, e_wlat, e_trans;
    Ctx() {
        cudaStreamCreateWithFlags(&s1, cudaStreamNonBlocking);
        cudaStreamCreateWithFlags(&s2, cudaStreamNonBlocking);
        cudaEventCreateWithFlags(&e_fork,  cudaEventDisableTiming);
        cudaEventCreateWithFlags(&e_win,   cudaEventDisableTiming);
        cudaEventCreateWithFlags(&e_wlat,  cudaEventDisableTiming);
        cudaEventCreateWithFlags(&e_trans, cudaEventDisableTiming);
    }
};
static Ctx g_ctx;

// ---------------- PTX helpers ------------------------------------------------
__device__ __forceinline__ void cp16(void* dst, const void* src) {
    uint32_t d = (uint32_t)__cvta_generic_to_shared(dst);
    asm volatile("cp.async.cg.shared.global [%0], [%1], 16;\n" :: "r"(d), "l"(src));
}
__device__ __forceinline__ void cp_commit() { asm volatile("cp.async.commit_group;\n"); }
__device__ __forceinline__ void cp_wait1()  { asm volatile("cp.async.wait_group 1;\n"); }

__device__ __forceinline__ void ldmx4(uint32_t* r, uint32_t addr) {
    asm volatile("ldmatrix.sync.aligned.m8n8.x4.shared.b16 {%0,%1,%2,%3}, [%4];\n"
                 : "=r"(r[0]), "=r"(r[1]), "=r"(r[2]), "=r"(r[3]) : "r"(addr));
}
__device__ __forceinline__ void ldmx4t(uint32_t* r, uint32_t addr) {
    asm volatile("ldmatrix.sync.aligned.m8n8.x4.trans.shared.b16 {%0,%1,%2,%3}, [%4];\n"
                 : "=r"(r[0]), "=r"(r[1]), "=r"(r[2]), "=r"(r[3]) : "r"(addr));
}
__device__ __forceinline__ void mma16816(float* c, const uint32_t* a, const uint32_t* b) {
    asm volatile(
        "mma.sync.aligned.m16n8k16.row.col.f32.f16.f16.f32 "
        "{%0,%1,%2,%3}, {%4,%5,%6,%7}, {%8,%9}, {%0,%1,%2,%3};\n"
        : "+f"(c[0]), "+f"(c[1]), "+f"(c[2]), "+f"(c[3])
        : "r"(a[0]), "r"(a[1]), "r"(a[2]), "r"(a[3]), "r"(b[0]), "r"(b[1]));
}

__device__ __forceinline__ float sigm(float x) { return 1.0f / (1.0f + __expf(-x)); }

// ---------------- mma.sync GEMM (champion config, plain launches) -------------
// MODE 0: plain store   1: C += acc   2: bias + permuted store to [B][T][OUT]
template<int BM, int BN, int WM, int WN, int MODE>
__global__ __launch_bounds__(WM * WN * 32, MODE == 1 ? 4 : 2) void mgemm(
    const __half* __restrict__ A, const __half* __restrict__ Bm,
    float* __restrict__ C, const float* __restrict__ bias,
    int M, int N, int K)
{
    constexpr int THREADS = WM * WN * 32;
    constexpr int RPW = BM / WM;
    constexpr int CPW = BN / WN;
    constexpr int MF  = RPW / 16;
    constexpr int NF  = CPW / 8;

    extern __shared__ __half smem[];
    __half* sA = smem;
    __half* sB = smem + STG * BM * 64;

    const int tid  = threadIdx.x;
    const int l    = tid & 31;
    const int warp = tid >> 5;
    const int wm   = (warp / WN) * RPW;
    const int wn   = (warp % WN) * CPW;
    const int bm   = blockIdx.y * BM;
    const int bn   = blockIdx.x * BN;

    float acc[MF][NF][4] = {};
    const int KT = K >> 6;

    auto load_stage = [&](int kt, int st) {
        const int k0 = kt << 6;
        constexpr int GA = BM * 8 / THREADS;
#pragma unroll
        for (int i = 0; i < GA; i++) {
            int c = tid + i * THREADS;
            int row = c >> 3, g = c & 7;
            cp16(sA + st * BM * 64 + row * 64 + ((g ^ (row & 7)) << 3),
                 A + (size_t)(bm + row) * K + k0 + (g << 3));
        }
        constexpr int GB = 8 * BN / THREADS;
#pragma unroll
        for (int i = 0; i < GB; i++) {
            int c = tid + i * THREADS;
            int k = c / (BN / 8), g = c % (BN / 8);
            int blk = g >> 3, gg = (g & 7) ^ (k & 7);
            cp16(sB + st * 64 * BN + k * BN + blk * 64 + (gg << 3),
                 Bm + (size_t)(k0 + k) * N + bn + (g << 3));
        }
    };

    load_stage(0, 0); cp_commit();
    load_stage(1, 1); cp_commit();

    for (int kt = 0; kt < KT; kt++) {
        const int st = kt % STG;
        cp_wait1();
        __syncthreads();
        if (kt + 2 < KT) load_stage(kt + 2, (kt + 2) % STG);
        cp_commit();

        uint32_t baseA = (uint32_t)__cvta_generic_to_shared(sA + st * BM * 64);
        uint32_t baseB = (uint32_t)__cvta_generic_to_shared(sB + st * 64 * BN);

#pragma unroll
        for (int kk = 0; kk < 4; kk++) {
            uint32_t a[MF][4];
#pragma unroll
            for (int i = 0; i < MF; i++) {
                int row = wm + i * 16 + (l & 15);
                int g   = kk * 2 + (l >> 4);
                ldmx4(a[i], baseA + (uint32_t)(row * 64 + ((g ^ (row & 7)) << 3)) * 2);
            }
            uint32_t b[NF / 2][4];
#pragma unroll
            for (int j = 0; j < NF / 2; j++) {
                int k = kk * 16 + (l & 15);
                int g = ((wn + j * 16) >> 3) + (l >> 4);
                int blk = g >> 3, gg = (g & 7) ^ (k & 7);
                ldmx4t(b[j], baseB + (uint32_t)(k * BN + blk * 64 + (gg << 3)) * 2);
            }
#pragma unroll
            for (int i = 0; i < MF; i++)
#pragma unroll
                for (int j = 0; j < NF / 2; j++) {
                    mma16816(acc[i][2 * j],     a[i], b[j]);
                    mma16816(acc[i][2 * j + 1], a[i], b[j] + 2);
                }
        }
    }

    const int r  = l >> 2;
    const int c0 = (l & 3) * 2;
#pragma unroll
    for (int i = 0; i < MF; i++) {
        int m0 = bm + wm + i * 16;
#pragma unroll
        for (int j = 0; j < NF; j++) {
            int col = bn + wn + j * 8 + c0;
#pragma unroll
            for (int h = 0; h < 2; h++) {
                int m = m0 + r + h * 8;
                float2 val = make_float2(acc[i][j][2 * h], acc[i][j][2 * h + 1]);
                if (MODE == 0) {
                    *reinterpret_cast<float2*>(&C[(size_t)m * N + col]) = val;
                } else if (MODE == 1) {
                    float2* p = reinterpret_cast<float2*>(&C[(size_t)m * N + col]);
                    float2 o = *p;
                    o.x += val.x; o.y += val.y;
                    *p = o;
                } else {
                    float2 bb = *reinterpret_cast<const float2*>(&bias[col]);
                    val.x += bb.x; val.y += bb.y;
                    int t = m >> 6, b0 = m & 63;
                    *reinterpret_cast<float2*>(
                        &C[((size_t)b0 * TT + t) * OUTF + col]) = val;
                }
            }
        }
    }
}

// ---------------- FUSED lateral GEMM + grid barrier + scan --------------------
// grid = (16, 20) = 320 CTAs x 128 threads. __launch_bounds__(128,4) guarantees
// 4 CTAs/SM (regs<=128, smem 48KB*4=192KB<=228KB) -> 592 slots >= 320 -> all
// CTAs co-resident in wave 1 -> spin barrier is deadlock-free.
__global__ __launch_bounds__(128, 4) void latscan_kernel(
    const __half* __restrict__ A,       // firing block blk-1  [1280][1024]
    const __half* __restrict__ Bm,      // Wlat [1024][1024]
    float* __restrict__ Csyn,           // syn + blk*MBLK*HID (accumulate)
    const float* __restrict__ syn_all,  // syn base
    const float* __restrict__ trans_k_m,
    const float* __restrict__ trans_asc_k,
    const float* __restrict__ asc_amp,
    const float* __restrict__ trans_asc_r,
    const float* __restrict__ thresh,
    __half* __restrict__ firing,
    float* __restrict__ volt_st, float* __restrict__ asc_st,
    float* __restrict__ fire_st, int t0, int* __restrict__ ctr)
{
    constexpr int BM = 64, BN = 64, THREADS = 128;
    constexpr int MF = 2, NF = 4;       // warp tile 32x32, 4 warps
    constexpr int Mk = MBLK, Nk = HID, Kk = HID;

    extern __shared__ __half smem[];
    __half* sA = smem;
    __half* sB = smem + STG * BM * 64;

    const int tid  = threadIdx.x;
    const int l    = tid & 31;
    const int warp = tid >> 5;
    const int wm   = (warp >> 1) * 32;
    const int wn   = (warp & 1) * 32;
    const int bm   = blockIdx.y * BM;
    const int bn   = blockIdx.x * BN;

    float acc[MF][NF][4] = {};
    const int KT = Kk >> 6;             // 16

    auto load_stage = [&](int kt, int st) {
        const int k0 = kt << 6;
#pragma unroll
        for (int i = 0; i < BM * 8 / THREADS; i++) {
            int c = tid + i * THREADS;
            int row = c >> 3, g = c & 7;
            cp16(sA + st * BM * 64 + row * 64 + ((g ^ (row & 7)) << 3),
                 A + (size_t)(bm + row) * Kk + k0 + (g << 3));
        }
#pragma unroll
        for (int i = 0; i < 8 * BN / THREADS; i++) {
            int c = tid + i * THREADS;
            int k = c / (BN / 8), g = c % (BN / 8);
            int blk = g >> 3, gg = (g & 7) ^ (k & 7);
            cp16(sB + st * 64 * BN + k * BN + blk * 64 + (gg << 3),
                 Bm + (size_t)(k0 + k) * Nk + bn + (g << 3));
        }
    };

    load_stage(0, 0); cp_commit();
    load_stage(1, 1); cp_commit();

    for (int kt = 0; kt < KT; kt++) {
        const int st = kt % STG;
        cp_wait1();
        __syncthreads();
        if (kt + 2 < KT) load_stage(kt + 2, (kt + 2) % STG);
        cp_commit();

        uint32_t baseA = (uint32_t)__cvta_generic_to_shared(sA + st * BM * 64);
        uint32_t baseB = (uint32_t)__cvta_generic_to_shared(sB + st * 64 * BN);

#pragma unroll
        for (int kk = 0; kk < 4; kk++) {
            uint32_t a[MF][4];
#pragma unroll
            for (int i = 0; i < MF; i++) {
                int row = wm + i * 16 + (l & 15);
                int g   = kk * 2 + (l >> 4);
                ldmx4(a[i], baseA + (uint32_t)(row * 64 + ((g ^ (row & 7)) << 3)) * 2);
            }
            uint32_t b[NF / 2][4];
#pragma unroll
            for (int j = 0; j < NF / 2; j++) {
                int k = kk * 16 + (l & 15);
                int g = ((wn + j * 16) >> 3) + (l >> 4);
                int blk = g >> 3, gg = (g & 7) ^ (k & 7);
                ldmx4t(b[j], baseB + (uint32_t)(k * BN + blk * 64 + (gg << 3)) * 2);
            }
#pragma unroll
            for (int i = 0; i < MF; i++)
#pragma unroll
                for (int j = 0; j < NF / 2; j++) {
                    mma16816(acc[i][2 * j],     a[i], b[j]);
                    mma16816(acc[i][2 * j + 1], a[i], b[j] + 2);
                }
        }
    }

    // epilogue: syn += lateral
    {
        const int r  = l >> 2;
        const int c0 = (l & 3) * 2;
#pragma unroll
        for (int i = 0; i < MF; i++) {
            int m0 = bm + wm + i * 16;
#pragma unroll
            for (int j = 0; j < NF; j++) {
                int col = bn + wn + j * 8 + c0;
#pragma unroll
                for (int h = 0; h < 2; h++) {
                    int m = m0 + r + h * 8;
                    float2* p = reinterpret_cast<float2*>(&Csyn[(size_t)m * Nk + col]);
                    float2 o = *p;
                    o.x += acc[i][j][2 * h];
                    o.y += acc[i][j][2 * h + 1];
                    *p = o;
                }
            }
        }
    }

    // ---- grid barrier: release stores, arrive, spin until all 320 arrived ----
    __threadfence();
    __syncthreads();
    if (tid == 0) {
        atomicAdd(ctr, 1);
        while (*(volatile int*)ctr < LAT_CTAS) __nanosleep(64);
    }
    __syncthreads();

    // ---- scan part: 40960 threads cover BH=65536 (2 interleaved elems) ------
    const int gid  = (blockIdx.y * 16 + blockIdx.x) * THREADS + tid;
    const int idx0 = gid;
    const int idx1 = gid + SCAN_THREADS;
    const bool has1 = idx1 < BH;
    const int h0 = idx0 & (HID - 1);
    const int h1 = idx1 & (HID - 1);

    float km0v = sigm(trans_k_m[h0]),  km1v = has1 ? sigm(trans_k_m[h1]) : 0.f;
    float c10 = 0.1f * km0v, c20 = 1.f - km0v;
    float c11 = 0.1f * km1v, c21 = 1.f - km1v;
    float ka00 = sigm(trans_asc_k[h0]),        ka01 = sigm(trans_asc_k[HID + h0]);
    float ka10 = has1 ? sigm(trans_asc_k[h1]) : 0.f;
    float ka11 = has1 ? sigm(trans_asc_k[HID + h1]) : 0.f;
    float am00 = asc_amp[h0], am01 = asc_amp[HID + h0];
    float am10 = has1 ? asc_amp[h1] : 0.f, am11 = has1 ? asc_amp[HID + h1] : 0.f;
    float r00 = 1.f - 2.f * sigm(trans_asc_r[h0]);
    float r01 = 1.f - 2.f * sigm(trans_asc_r[HID + h0]);
    float r10 = has1 ? 1.f - 2.f * sigm(trans_asc_r[h1]) : 0.f;
    float r11 = has1 ? 1.f - 2.f * sigm(trans_asc_r[HID + h1]) : 0.f;
    float th0 = thresh[h0], th1 = has1 ? thresh[h1] : 0.f;

    float f0 = fire_st[idx0], v0 = volt_st[idx0];
    float a00 = asc_st[idx0], a01 = asc_st[BH + idx0];
    float f1 = 0.f, v1 = 0.f, a10 = 0.f, a11 = 0.f;
    if (has1) {
        f1 = fire_st[idx1]; v1 = volt_st[idx1];
        a10 = asc_st[idx1]; a11 = asc_st[BH + idx1];
    }

#pragma unroll
    for (int s = 0; s < DELAYS; s++) {
        float sy0 = syn_all[(size_t)(t0 + s) * BH + idx0];
        float sy1 = has1 ? syn_all[(size_t)(t0 + s) * BH + idx1] : 0.f;
        a00 = (am00 + r00 * a00) * f0 * ka00 + (1.f - ka00) * a00;
        a10 = (am10 + r10 * a10) * f1 * ka10 + (1.f - ka10) * a10;
        a01 = (am01 + r01 * a01) * f0 * ka01 + (1.f - ka01) * a01;
        a11 = (am11 + r11 * a11) * f1 * ka11 + (1.f - ka11) * a11;
        v0 = c10 * (sy0 + a00 + a01) + c20 * v0;
        v1 = c11 * (sy1 + a10 + a11) + c21 * v1;
        f0 = sigm(v0 - th0);
        f1 = sigm(v1 - th1);
        firing[(size_t)(t0 + s) * BH + idx0] = __float2half(f0);
        if (has1) firing[(size_t)(t0 + s) * BH + idx1] = __float2half(f1);
    }
    fire_st[idx0] = f0; volt_st[idx0] = v0;
    asc_st[idx0] = a00; asc_st[BH + idx0] = a01;
    if (has1) {
        fire_st[idx1] = f1; volt_st[idx1] = v1;
        asc_st[idx1] = a10; asc_st[BH + idx1] = a11;
    }
}

// ---------------- conversion kernels -----------------------------------------
__global__ __launch_bounds__(256) void convx_kernel(const float* __restrict__ x,
                                                    __half* __restrict__ xh)
{
    if (blockIdx.x == 0 && threadIdx.x < NBLK) g_ctr[threadIdx.x] = 0;
    int i  = blockIdx.x * 256 + threadIdx.x;
    int i4 = i % (INF / 4);
    int bt = i / (INF / 4);
    int b = bt / TT, t = bt % TT;
    float4 v = reinterpret_cast<const float4*>(x)[i];
    int dst = (t * BB + b) * (INF / 4) + i4;
    reinterpret_cast<__half2*>(xh)[2 * dst + 0] = __floats2half2_rn(v.x, v.y);
    reinterpret_cast<__half2*>(xh)[2 * dst + 1] = __floats2half2_rn(v.z, v.w);
}

__global__ __launch_bounds__(256) void f2h_kernel(const float* __restrict__ in,
                                                  __half* __restrict__ out)
{
    int i = blockIdx.x * 256 + threadIdx.x;
    float4 v = reinterpret_cast<const float4*>(in)[i];
    reinterpret_cast<__half2*>(out)[2 * i + 0] = __floats2half2_rn(v.x, v.y);
    reinterpret_cast<__half2*>(out)[2 * i + 1] = __floats2half2_rn(v.z, v.w);
}

__global__ void transp_kernel(const float* __restrict__ w, __half* __restrict__ wt)
{
    __shared__ float tile[32][33];
    int ox = blockIdx.x * 32, hy = blockIdx.y * 32;
    int tx = threadIdx.x, ty = threadIdx.y;
#pragma unroll
    for (int rr = 0; rr < 32; rr += 8)
        tile[ty + rr][tx] = w[(size_t)(ox + ty + rr) * HID + hy + tx];
    __syncthreads();
#pragma unroll
    for (int rr = 0; rr < 32; rr += 8)
        wt[(size_t)(hy + ty + rr) * OUTF + ox + tx] = __float2half(tile[tx][ty + rr]);
}

// ---------------- standalone scan (block 0 only) ------------------------------
__global__ __launch_bounds__(256) void scan_kernel(
    const float* __restrict__ syn_all,
    const float* __restrict__ trans_k_m,
    const float* __restrict__ trans_asc_k,
    const float* __restrict__ asc_amp,
    const float* __restrict__ trans_asc_r,
    const float* __restrict__ thresh,
    __half* __restrict__ firing,
    float* __restrict__ volt_st, float* __restrict__ asc_st,
    float* __restrict__ fire_st)
{
    int idx = blockIdx.x * blockDim.x + threadIdx.x;
    int h = idx & (HID - 1);

    float syn[DELAYS];
#pragma unroll
    for (int s = 0; s < DELAYS; s++)
        syn[s] = syn_all[(size_t)s * BH + idx];

    float km  = sigm(trans_k_m[h]);
    float c1  = 0.1f * km;
    float c2  = 1.0f - km;
    float ka0 = sigm(trans_asc_k[h]);
    float ka1 = sigm(trans_asc_k[HID + h]);
    float amp0 = asc_amp[h],       amp1 = asc_amp[HID + h];
    float r0 = 1.0f - 2.0f * sigm(trans_asc_r[h]);
    float r1 = 1.0f - 2.0f * sigm(trans_asc_r[HID + h]);
    float th = thresh[h];

    float f = 0.f, v = 0.f, a0 = 0.f, a1 = 0.f;

#pragma unroll
    for (int s = 0; s < DELAYS; s++) {
        a0 = (amp0 + r0 * a0) * f * ka0 + (1.0f - ka0) * a0;
        a1 = (amp1 + r1 * a1) * f * ka1 + (1.0f - ka1) * a1;
        v  = c1 * (syn[s] + a0 + a1) + c2 * v;
        f  = sigm(v - th);
        firing[(size_t)s * BH + idx] = __float2half(f);
    }
    fire_st[idx] = f;
    volt_st[idx] = v;
    asc_st[idx] = a0;
    asc_st[BH + idx] = a1;
}

// ---------------- launch ------------------------------------------------------
extern "C" void kernel_launch(void* const* d_in, const int* in_sizes, int n_in,
                              void* d_out, int out_size)
{
    const float* x           = (const float*)d_in[0];
    const float* W_in        = (const float*)d_in[1];
    const float* W_lat       = (const float*)d_in[2];
    const float* thresh      = (const float*)d_in[3];
    const float* trans_k_m   = (const float*)d_in[4];
    const float* trans_asc_k = (const float*)d_in[5];
    const float* asc_amp     = (const float*)d_in[6];
    const float* trans_asc_r = (const float*)d_in[7];
    const float* W_out       = (const float*)d_in[8];
    const float* b_out       = (const float*)d_in[9];
    float* out = (float*)d_out;

    __half *xh, *Win, *Wlat, *WoutT, *firing;
    float *syn, *volt, *asc, *fire;
    int* ctr;
    cudaGetSymbolAddress((void**)&xh,     g_xh);
    cudaGetSymbolAddress((void**)&Win,    g_Win);
    cudaGetSymbolAddress((void**)&Wlat,   g_Wlat);
    cudaGetSymbolAddress((void**)&WoutT,  g_WoutT);
    cudaGetSymbolAddress((void**)&syn,    g_syn);
    cudaGetSymbolAddress((void**)&firing, g_firing);
    cudaGetSymbolAddress((void**)&volt,   g_volt);
    cudaGetSymbolAddress((void**)&asc,    g_asc);
    cudaGetSymbolAddress((void**)&fire,   g_fire);
    cudaGetSymbolAddress((void**)&ctr,    g_ctr);

    const int SM_BIG = STG * (128 * 64 + 64 * 128) * 2;   // 98304
    const int SM_LAT = STG * (64 * 64 + 64 * 64) * 2;     // 49152
    cudaFuncSetAttribute(mgemm<128, 128, 4, 2, 0>,
                         cudaFuncAttributeMaxDynamicSharedMemorySize, SM_BIG);
    cudaFuncSetAttribute(mgemm<128, 128, 4, 2, 2>,
                         cudaFuncAttributeMaxDynamicSharedMemorySize, SM_BIG);
    cudaFuncSetAttribute(latscan_kernel,
                         cudaFuncAttributeMaxDynamicSharedMemorySize, SM_LAT);

    cudaStream_t s0 = 0, s1 = g_ctx.s1, s2 = g_ctx.s2;

    // ---- fork event FIRST (capture-legal fork of side streams) ----
    cudaEventRecord(g_ctx.e_fork, s0);

    // ---- s1: weight fp16 conversions ----
    cudaStreamWaitEvent(s1, g_ctx.e_fork, 0);
    f2h_kernel<<<(INF * HID / 4) / 256, 256, 0, s1>>>(W_in, Win);
    cudaEventRecord(g_ctx.e_win, s1);
    f2h_kernel<<<(HID * HID / 4) / 256, 256, 0, s1>>>(W_lat, Wlat);
    cudaEventRecord(g_ctx.e_wlat, s1);

    // ---- s2: W_out transpose ----
    cudaStreamWaitEvent(s2, g_ctx.e_fork, 0);
    transp_kernel<<<dim3(OUTF / 32, HID / 32), dim3(32, 8), 0, s2>>>(W_out, WoutT);
    cudaEventRecord(g_ctx.e_trans, s2);

    // ---- main stream: sequential chain with fused lateral+scan ----
    convx_kernel<<<(BB * TT * INF / 4) / 256, 256, 0, s0>>>(x, xh);
    cudaStreamWaitEvent(s0, g_ctx.e_win, 0);
    mgemm<128, 128, 4, 2, 0><<<dim3(HID / 128, (BB * TT) / 128), 256, SM_BIG, s0>>>(
        xh, Win, syn, nullptr, BB * TT, HID, INF);
    cudaStreamWaitEvent(s0, g_ctx.e_wlat, 0);

    scan_kernel<<<BH / 256, 256, 0, s0>>>(
        syn, trans_k_m, trans_asc_k, asc_amp, trans_asc_r, thresh,
        firing, volt, asc, fire);

    for (int blk = 1; blk < NBLK; blk++) {
        latscan_kernel<<<dim3(HID / 64, MBLK / 64), 128, SM_LAT, s0>>>(
            firing + (size_t)(blk - 1) * MBLK * HID, Wlat,
            syn + (size_t)blk * MBLK * HID, syn,
            trans_k_m, trans_asc_k, asc_amp, trans_asc_r, thresh,
            firing, volt, asc, fire, blk * DELAYS, ctr + blk - 1);
    }

    // ---- readout: single full GEMM with fused bias + permute ----
    cudaStreamWaitEvent(s0, g_ctx.e_trans, 0);
    mgemm<128, 128, 4, 2, 2><<<dim3(OUTF / 128, (BB * TT) / 128), 256, SM_BIG, s0>>>(
        firing, WoutT, out, b_out, BB * TT, OUTF, HID);
}

// round 16
// speedup vs baseline: 1.2175x; 1.2018x over previous
#include <cuda_runtime.h>
#include <cuda_fp16.h>
#include <cstdint>

#define BB   64
#define TT   200
#define INF  512
#define HID  1024
#define OUTF 512
#define DELAYS 20
#define BH   (BB * HID)          // 65536
#define NBLK (TT / DELAYS)       // 10
#define MBLK (DELAYS * BB)       // 1280
#define STG  3
#define KCAT (HID + INF)         // 1536

// ---------------- scratch (device globals) ----------------------------------
__device__ __half g_xh[(size_t)TT * BB * INF];    // permuted fp16 input [t*64+b][IN]
__device__ __half g_Wcat[(size_t)KCAT * HID];     // [Wlat(1024) ; Win(512)] rows x 1024
__device__ __half g_WoutT[(size_t)HID * OUTF];    // [H][O]
__device__ float  g_syn[(size_t)TT * BH];
__device__ __half g_firing[(size_t)TT * BH];
__device__ float  g_volt[BH];
__device__ float  g_asc[2 * BH];
__device__ float  g_fire[BH];

// ---------------- PTX helpers ------------------------------------------------
__device__ __forceinline__ void cp16(void* dst, const void* src) {
    uint32_t d = (uint32_t)__cvta_generic_to_shared(dst);
    asm volatile("cp.async.cg.shared.global [%0], [%1], 16;\n" :: "r"(d), "l"(src));
}
__device__ __forceinline__ void cp_commit() { asm volatile("cp.async.commit_group;\n"); }
__device__ __forceinline__ void cp_wait1()  { asm volatile("cp.async.wait_group 1;\n"); }

__device__ __forceinline__ void ldmx4(uint32_t* r, uint32_t addr) {
    asm volatile("ldmatrix.sync.aligned.m8n8.x4.shared.b16 {%0,%1,%2,%3}, [%4];\n"
                 : "=r"(r[0]), "=r"(r[1]), "=r"(r[2]), "=r"(r[3]) : "r"(addr));
}
__device__ __forceinline__ void ldmx4t(uint32_t* r, uint32_t addr) {
    asm volatile("ldmatrix.sync.aligned.m8n8.x4.trans.shared.b16 {%0,%1,%2,%3}, [%4];\n"
                 : "=r"(r[0]), "=r"(r[1]), "=r"(r[2]), "=r"(r[3]) : "r"(addr));
}
__device__ __forceinline__ void mma16816(float* c, const uint32_t* a, const uint32_t* b) {
    asm volatile(
        "mma.sync.aligned.m16n8k16.row.col.f32.f16.f16.f32 "
        "{%0,%1,%2,%3}, {%4,%5,%6,%7}, {%8,%9}, {%0,%1,%2,%3};\n"
        : "+f"(c[0]), "+f"(c[1]), "+f"(c[2]), "+f"(c[3])
        : "r"(a[0]), "r"(a[1]), "r"(a[2]), "r"(a[3]), "r"(b[0]), "r"(b[1]));
}

__device__ __forceinline__ float sigm(float x) { return 1.0f / (1.0f + __expf(-x)); }

// ---------------- mma.sync GEMM (champion config) -----------------------------
// MODE 0: plain store   2: bias + permuted store to [B][T][OUT]
template<int BM, int BN, int WM, int WN, int MODE>
__global__ __launch_bounds__(WM * WN * 32, 2) void mgemm(
    const __half* __restrict__ A, const __half* __restrict__ Bm,
    float* __restrict__ C, const float* __restrict__ bias,
    int M, int N, int K)
{
    constexpr int THREADS = WM * WN * 32;
    constexpr int RPW = BM / WM;
    constexpr int CPW = BN / WN;
    constexpr int MF  = RPW / 16;
    constexpr int NF  = CPW / 8;

    extern __shared__ __half smem[];
    __half* sA = smem;
    __half* sB = smem + STG * BM * 64;

    const int tid  = threadIdx.x;
    const int l    = tid & 31;
    const int warp = tid >> 5;
    const int wm   = (warp / WN) * RPW;
    const int wn   = (warp % WN) * CPW;
    const int bm   = blockIdx.y * BM;
    const int bn   = blockIdx.x * BN;

    float acc[MF][NF][4] = {};
    const int KT = K >> 6;

    auto load_stage = [&](int kt, int st) {
        const int k0 = kt << 6;
        constexpr int GA = BM * 8 / THREADS;
#pragma unroll
        for (int i = 0; i < GA; i++) {
            int c = tid + i * THREADS;
            int row = c >> 3, g = c & 7;
            cp16(sA + st * BM * 64 + row * 64 + ((g ^ (row & 7)) << 3),
                 A + (size_t)(bm + row) * K + k0 + (g << 3));
        }
        constexpr int GB = 8 * BN / THREADS;
#pragma unroll
        for (int i = 0; i < GB; i++) {
            int c = tid + i * THREADS;
            int k = c / (BN / 8), g = c % (BN / 8);
            int blk = g >> 3, gg = (g & 7) ^ (k & 7);
            cp16(sB + st * 64 * BN + k * BN + blk * 64 + (gg << 3),
                 Bm + (size_t)(k0 + k) * N + bn + (g << 3));
        }
    };

    load_stage(0, 0); cp_commit();
    load_stage(1, 1); cp_commit();

    for (int kt = 0; kt < KT; kt++) {
        const int st = kt % STG;
        cp_wait1();
        __syncthreads();
        if (kt + 2 < KT) load_stage(kt + 2, (kt + 2) % STG);
        cp_commit();

        uint32_t baseA = (uint32_t)__cvta_generic_to_shared(sA + st * BM * 64);
        uint32_t baseB = (uint32_t)__cvta_generic_to_shared(sB + st * 64 * BN);

#pragma unroll
        for (int kk = 0; kk < 4; kk++) {
            uint32_t a[MF][4];
#pragma unroll
            for (int i = 0; i < MF; i++) {
                int row = wm + i * 16 + (l & 15);
                int g   = kk * 2 + (l >> 4);
                ldmx4(a[i], baseA + (uint32_t)(row * 64 + ((g ^ (row & 7)) << 3)) * 2);
            }
            uint32_t b[NF / 2][4];
#pragma unroll
            for (int j = 0; j < NF / 2; j++) {
                int k = kk * 16 + (l & 15);
                int g = ((wn + j * 16) >> 3) + (l >> 4);
                int blk = g >> 3, gg = (g & 7) ^ (k & 7);
                ldmx4t(b[j], baseB + (uint32_t)(k * BN + blk * 64 + (gg << 3)) * 2);
            }
#pragma unroll
            for (int i = 0; i < MF; i++)
#pragma unroll
                for (int j = 0; j < NF / 2; j++) {
                    mma16816(acc[i][2 * j],     a[i], b[j]);
                    mma16816(acc[i][2 * j + 1], a[i], b[j] + 2);
                }
        }
    }

    const int r  = l >> 2;
    const int c0 = (l & 3) * 2;
#pragma unroll
    for (int i = 0; i < MF; i++) {
        int m0 = bm + wm + i * 16;
#pragma unroll
        for (int j = 0; j < NF; j++) {
            int col = bn + wn + j * 8 + c0;
#pragma unroll
            for (int h = 0; h < 2; h++) {
                int m = m0 + r + h * 8;
                float2 val = make_float2(acc[i][j][2 * h], acc[i][j][2 * h + 1]);
                if (MODE == 0) {
                    *reinterpret_cast<float2*>(&C[(size_t)m * N + col]) = val;
                } else {
                    float2 bb = *reinterpret_cast<const float2*>(&bias[col]);
                    val.x += bb.x; val.y += bb.y;
                    int t = m >> 6, b0 = m & 63;
                    *reinterpret_cast<float2*>(
                        &C[((size_t)b0 * TT + t) * OUTF + col]) = val;
                }
            }
        }
    }
}

// ---------------- K-concat lateral GEMM --------------------------------------
// syn_blk[m][n] = sum_k firing_prev[m][k]*Wlat[k][n] + sum_j xh_blk[m][j]*Win[j][n]
// A1 = firing_prev [1280][1024], A2 = xh_blk [1280][512], B = Wcat [1536][1024]
// 64x64 tile, 128 threads, warp 32x32 (exact champion lateral core), K=1536.
__global__ __launch_bounds__(128, 4) void latcat_kernel(
    const __half* __restrict__ A1, const __half* __restrict__ A2,
    const __half* __restrict__ Bm, float* __restrict__ C)
{
    constexpr int BM = 64, BN = 64, THREADS = 128;
    constexpr int MF = 2, NF = 4;

    extern __shared__ __half smem[];
    __half* sA = smem;                    // [STG][64*64]
    __half* sB = smem + STG * BM * 64;    // [STG][64*64]

    const int tid  = threadIdx.x;
    const int l    = tid & 31;
    const int warp = tid >> 5;
    const int wm   = (warp >> 1) * 32;
    const int wn   = (warp & 1) * 32;
    const int bm   = blockIdx.y * BM;
    const int bn   = blockIdx.x * BN;

    float acc[MF][NF][4] = {};
    const int KT = KCAT >> 6;   // 24

    auto load_stage = [&](int kt, int st) {
        const int k0 = kt << 6;
#pragma unroll
        for (int i = 0; i < 4; i++) {                 // A: 64x64 halves
            int c = tid + i * THREADS;
            int row = c >> 3, g = c & 7;
            const __half* src = (k0 < HID)
                ? A1 + (size_t)(bm + row) * HID + k0 + (g << 3)
                : A2 + (size_t)(bm + row) * INF + (k0 - HID) + (g << 3);
            cp16(sA + st * BM * 64 + row * 64 + ((g ^ (row & 7)) << 3), src);
        }
#pragma unroll
        for (int i = 0; i < 4; i++) {                 // B: 64 rows x 64 cols
            int c = tid + i * THREADS;
            int k = c >> 3, g = c & 7;
            int gg = (g & 7) ^ (k & 7);
            cp16(sB + st * 64 * BN + k * BN + (gg << 3),
                 Bm + (size_t)(k0 + k) * HID + bn + (g << 3));
        }
    };

    load_stage(0, 0); cp_commit();
    load_stage(1, 1); cp_commit();

    for (int kt = 0; kt < KT; kt++) {
        const int st = kt % STG;
        cp_wait1();
        __syncthreads();
        if (kt + 2 < KT) load_stage(kt + 2, (kt + 2) % STG);
        cp_commit();

        uint32_t baseA = (uint32_t)__cvta_generic_to_shared(sA + st * BM * 64);
        uint32_t baseB = (uint32_t)__cvta_generic_to_shared(sB + st * 64 * BN);

#pragma unroll
        for (int kk = 0; kk < 4; kk++) {
            uint32_t a[MF][4];
#pragma unroll
            for (int i = 0; i < MF; i++) {
                int row = wm + i * 16 + (l & 15);
                int g   = kk * 2 + (l >> 4);
                ldmx4(a[i], baseA + (uint32_t)(row * 64 + ((g ^ (row & 7)) << 3)) * 2);
            }
            uint32_t b[NF / 2][4];
#pragma unroll
            for (int j = 0; j < NF / 2; j++) {
                int k = kk * 16 + (l & 15);
                int g = ((wn + j * 16) >> 3) + (l >> 4);
                int gg = (g & 7) ^ (k & 7);
                ldmx4t(b[j], baseB + (uint32_t)(k * BN + (gg << 3)) * 2);
            }
#pragma unroll
            for (int i = 0; i < MF; i++)
#pragma unroll
                for (int j = 0; j < NF / 2; j++) {
                    mma16816(acc[i][2 * j],     a[i], b[j]);
                    mma16816(acc[i][2 * j + 1], a[i], b[j] + 2);
                }
        }
    }

    // plain store (syn for this block is produced wholly here)
    const int r  = l >> 2;
    const int c0 = (l & 3) * 2;
#pragma unroll
    for (int i = 0; i < MF; i++) {
        int m0 = bm + wm + i * 16;
#pragma unroll
        for (int j = 0; j < NF; j++) {
            int col = bn + wn + j * 8 + c0;
#pragma unroll
            for (int h = 0; h < 2; h++) {
                int m = m0 + r + h * 8;
                *reinterpret_cast<float2*>(&C[(size_t)m * HID + col]) =
                    make_float2(acc[i][j][2 * h], acc[i][j][2 * h + 1]);
            }
        }
    }
}

// ---------------- conversion kernels -----------------------------------------
__global__ __launch_bounds__(256) void convx_kernel(const float* __restrict__ x,
                                                    __half* __restrict__ xh)
{
    int i  = blockIdx.x * 256 + threadIdx.x;
    int i4 = i % (INF / 4);
    int bt = i / (INF / 4);
    int b = bt / TT, t = bt % TT;
    float4 v = reinterpret_cast<const float4*>(x)[i];
    int dst = (t * BB + b) * (INF / 4) + i4;
    reinterpret_cast<__half2*>(xh)[2 * dst + 0] = __floats2half2_rn(v.x, v.y);
    reinterpret_cast<__half2*>(xh)[2 * dst + 1] = __floats2half2_rn(v.z, v.w);
}

__global__ __launch_bounds__(256) void f2h_kernel(const float* __restrict__ in,
                                                  __half* __restrict__ out)
{
    int i = blockIdx.x * 256 + threadIdx.x;
    float4 v = reinterpret_cast<const float4*>(in)[i];
    reinterpret_cast<__half2*>(out)[2 * i + 0] = __floats2half2_rn(v.x, v.y);
    reinterpret_cast<__half2*>(out)[2 * i + 1] = __floats2half2_rn(v.z, v.w);
}

// W_out [OUT][HID] fp32 -> WoutT [HID][OUT] fp16
__global__ void transp_kernel(const float* __restrict__ w, __half* __restrict__ wt)
{
    __shared__ float tile[32][33];
    int ox = blockIdx.x * 32, hy = blockIdx.y * 32;
    int tx = threadIdx.x, ty = threadIdx.y;
#pragma unroll
    for (int rr = 0; rr < 32; rr += 8)
        tile[ty + rr][tx] = w[(size_t)(ox + ty + rr) * HID + hy + tx];
    __syncthreads();
#pragma unroll
    for (int rr = 0; rr < 32; rr += 8)
        wt[(size_t)(hy + ty + rr) * OUTF + ox + tx] = __float2half(tile[tx][ty + rr]);
}

// ---------------- elementwise 20-step scan (exact champion) -------------------
__global__ __launch_bounds__(256) void scan_kernel(
    const float* __restrict__ syn_all,
    const float* __restrict__ trans_k_m,
    const float* __restrict__ trans_asc_k,
    const float* __restrict__ asc_amp,
    const float* __restrict__ trans_asc_r,
    const float* __restrict__ thresh,
    __half* __restrict__ firing,
    float* __restrict__ volt_st, float* __restrict__ asc_st,
    float* __restrict__ fire_st, int t0)
{
    int idx = blockIdx.x * blockDim.x + threadIdx.x;
    int h = idx & (HID - 1);

    float syn[DELAYS];
#pragma unroll
    for (int s = 0; s < DELAYS; s++)
        syn[s] = syn_all[(size_t)(t0 + s) * BH + idx];

    float km  = sigm(trans_k_m[h]);
    float c1  = 0.1f * km;
    float c2  = 1.0f - km;
    float ka0 = sigm(trans_asc_k[h]);
    float ka1 = sigm(trans_asc_k[HID + h]);
    float amp0 = asc_amp[h],       amp1 = asc_amp[HID + h];
    float r0 = 1.0f - 2.0f * sigm(trans_asc_r[h]);
    float r1 = 1.0f - 2.0f * sigm(trans_asc_r[HID + h]);
    float th = thresh[h];

    float f, v, a0, a1;
    if (t0 == 0) {
        f = 0.f; v = 0.f; a0 = 0.f; a1 = 0.f;
    } else {
        f  = fire_st[idx];
        v  = volt_st[idx];
        a0 = asc_st[idx];
        a1 = asc_st[BH + idx];
    }

#pragma unroll
    for (int s = 0; s < DELAYS; s++) {
        a0 = (amp0 + r0 * a0) * f * ka0 + (1.0f - ka0) * a0;
        a1 = (amp1 + r1 * a1) * f * ka1 + (1.0f - ka1) * a1;
        v  = c1 * (syn[s] + a0 + a1) + c2 * v;
        f  = sigm(v - th);
        firing[(size_t)(t0 + s) * BH + idx] = __float2half(f);
    }
    fire_st[idx] = f;
    volt_st[idx] = v;
    asc_st[idx] = a0;
    asc_st[BH + idx] = a1;
}

// ---------------- launch (single stream, R3-style) ----------------------------
extern "C" void kernel_launch(void* const* d_in, const int* in_sizes, int n_in,
                              void* d_out, int out_size)
{
    const float* x           = (const float*)d_in[0];
    const float* W_in        = (const float*)d_in[1];
    const float* W_lat       = (const float*)d_in[2];
    const float* thresh      = (const float*)d_in[3];
    const float* trans_k_m   = (const float*)d_in[4];
    const float* trans_asc_k = (const float*)d_in[5];
    const float* asc_amp     = (const float*)d_in[6];
    const float* trans_asc_r = (const float*)d_in[7];
    const float* W_out       = (const float*)d_in[8];
    const float* b_out       = (const float*)d_in[9];
    float* out = (float*)d_out;

    __half *xh, *Wcat, *WoutT, *firing;
    float *syn, *volt, *asc, *fire;
    cudaGetSymbolAddress((void**)&xh,     g_xh);
    cudaGetSymbolAddress((void**)&Wcat,   g_Wcat);
    cudaGetSymbolAddress((void**)&WoutT,  g_WoutT);
    cudaGetSymbolAddress((void**)&syn,    g_syn);
    cudaGetSymbolAddress((void**)&firing, g_firing);
    cudaGetSymbolAddress((void**)&volt,   g_volt);
    cudaGetSymbolAddress((void**)&asc,    g_asc);
    cudaGetSymbolAddress((void**)&fire,   g_fire);

    const int SM_BIG = STG * (128 * 64 + 64 * 128) * 2;   // 98304
    const int SM_LAT = STG * (64 * 64 + 64 * 64) * 2;     // 49152
    cudaFuncSetAttribute(mgemm<128, 128, 4, 2, 0>,
                         cudaFuncAttributeMaxDynamicSharedMemorySize, SM_BIG);
    cudaFuncSetAttribute(mgemm<128, 128, 4, 2, 2>,
                         cudaFuncAttributeMaxDynamicSharedMemorySize, SM_BIG);
    cudaFuncSetAttribute(latcat_kernel,
                         cudaFuncAttributeMaxDynamicSharedMemorySize, SM_LAT);

    // ---- preamble (all default stream, serial) ----
    convx_kernel<<<(BB * TT * INF / 4) / 256, 256>>>(x, xh);
    f2h_kernel<<<(HID * HID / 4) / 256, 256>>>(W_lat, Wcat);                 // rows 0..1023
    f2h_kernel<<<(INF * HID / 4) / 256, 256>>>(W_in, Wcat + (size_t)HID * HID); // rows 1024..1535
    transp_kernel<<<dim3(OUTF / 32, HID / 32), dim3(32, 8)>>>(W_out, WoutT);

    // ---- block 0 input projection only (M=1280, K=512) ----
    mgemm<128, 128, 4, 2, 0><<<dim3(HID / 128, MBLK / 128), 256, SM_BIG>>>(
        xh, Wcat + (size_t)HID * HID, syn, nullptr, MBLK, HID, INF);

    // ---- recurrent chain: K-concat lateral (xproj folded in) + scan ----
    for (int blk = 0; blk < NBLK; blk++) {
        if (blk > 0) {
            latcat_kernel<<<dim3(HID / 64, MBLK / 64), 128, SM_LAT>>>(
                firing + (size_t)(blk - 1) * MBLK * HID,
                xh + (size_t)blk * MBLK * INF,
                Wcat,
                syn + (size_t)blk * MBLK * HID);
        }
        scan_kernel<<<BH / 256, 256>>>(
            syn, trans_k_m, trans_asc_k, asc_amp, trans_asc_r, thresh,
            firing, volt, asc, fire, blk * DELAYS);
    }

    // ---- readout: single full GEMM with fused bias + permute ----
    mgemm<128, 128, 4, 2, 2><<<dim3(OUTF / 128, (BB * TT) / 128), 256, SM_BIG>>>(
        firing, WoutT, out, b_out, BB * TT, OUTF, HID);
}

// round 17
// speedup vs baseline: 1.2651x; 1.0391x over previous
#include <cuda_runtime.h>
#include <cuda_fp16.h>
#include <cstdint>

#define BB   64
#define TT   200
#define INF  512
#define HID  1024
#define OUTF 512
#define DELAYS 20
#define BH   (BB * HID)          // 65536
#define NBLK (TT / DELAYS)       // 10
#define MBLK (DELAYS * BB)       // 1280
#define STG  3
#define KCAT (HID + INF)         // 1536

// ---------------- scratch (device globals) ----------------------------------
__device__ __half g_xh[(size_t)TT * BB * INF];
__device__ __half g_Wcat[(size_t)KCAT * HID];     // [Wlat(1024) ; Win(512)]
__device__ __half g_WoutT[(size_t)HID * OUTF];
__device__ float  g_syn[(size_t)TT * BH];
__device__ __half g_firing[(size_t)TT * BH];
__device__ float  g_volt[BH];
__device__ float  g_asc[2 * BH];
__device__ float  g_fire[BH];

// ---------------- PTX helpers ------------------------------------------------
__device__ __forceinline__ void cp16(void* dst, const void* src) {
    uint32_t d = (uint32_t)__cvta_generic_to_shared(dst);
    asm volatile("cp.async.cg.shared.global [%0], [%1], 16;\n" :: "r"(d), "l"(src));
}
__device__ __forceinline__ void cp_commit() { asm volatile("cp.async.commit_group;\n"); }
__device__ __forceinline__ void cp_wait1()  { asm volatile("cp.async.wait_group 1;\n"); }

__device__ __forceinline__ void ldmx4(uint32_t* r, uint32_t addr) {
    asm volatile("ldmatrix.sync.aligned.m8n8.x4.shared.b16 {%0,%1,%2,%3}, [%4];\n"
                 : "=r"(r[0]), "=r"(r[1]), "=r"(r[2]), "=r"(r[3]) : "r"(addr));
}
__device__ __forceinline__ void ldmx4t(uint32_t* r, uint32_t addr) {
    asm volatile("ldmatrix.sync.aligned.m8n8.x4.trans.shared.b16 {%0,%1,%2,%3}, [%4];\n"
                 : "=r"(r[0]), "=r"(r[1]), "=r"(r[2]), "=r"(r[3]) : "r"(addr));
}
__device__ __forceinline__ void mma16816(float* c, const uint32_t* a, const uint32_t* b) {
    asm volatile(
        "mma.sync.aligned.m16n8k16.row.col.f32.f16.f16.f32 "
        "{%0,%1,%2,%3}, {%4,%5,%6,%7}, {%8,%9}, {%0,%1,%2,%3};\n"
        : "+f"(c[0]), "+f"(c[1]), "+f"(c[2]), "+f"(c[3])
        : "r"(a[0]), "r"(a[1]), "r"(a[2]), "r"(a[3]), "r"(b[0]), "r"(b[1]));
}

__device__ __forceinline__ float sigm(float x) { return 1.0f / (1.0f + __expf(-x)); }

// ---------------- 64x64 / 128-thread GEMM (champion lateral core) -------------
// C[M,N] = A[M,K(lda)] @ B[K,N]  (B row stride == N)
// MODE 0: plain store    MODE 2: bias + permuted store to out[b][t][OUT]
template<int MODE>
__global__ __launch_bounds__(128, 4) void mgemm64(
    const __half* __restrict__ A, const __half* __restrict__ Bm,
    float* __restrict__ C, const float* __restrict__ bias,
    int M, int N, int K, int lda)
{
    constexpr int BM = 64, BN = 64, THREADS = 128;
    constexpr int MF = 2, NF = 4;

    extern __shared__ __half smem[];
    __half* sA = smem;                    // [STG][64*64]
    __half* sB = smem + STG * BM * 64;    // [STG][64*64]

    const int tid  = threadIdx.x;
    const int l    = tid & 31;
    const int warp = tid >> 5;
    const int wm   = (warp >> 1) * 32;
    const int wn   = (warp & 1) * 32;
    const int bm   = blockIdx.y * BM;
    const int bn   = blockIdx.x * BN;

    float acc[MF][NF][4] = {};
    const int KT = K >> 6;

    auto load_stage = [&](int kt, int st) {
        const int k0 = kt << 6;
#pragma unroll
        for (int i = 0; i < 4; i++) {
            int c = tid + i * THREADS;
            int row = c >> 3, g = c & 7;
            cp16(sA + st * BM * 64 + row * 64 + ((g ^ (row & 7)) << 3),
                 A + (size_t)(bm + row) * lda + k0 + (g << 3));
        }
#pragma unroll
        for (int i = 0; i < 4; i++) {
            int c = tid + i * THREADS;
            int k = c >> 3, g = c & 7;
            int gg = (g & 7) ^ (k & 7);
            cp16(sB + st * 64 * BN + k * BN + (gg << 3),
                 Bm + (size_t)(k0 + k) * N + bn + (g << 3));
        }
    };

    load_stage(0, 0); cp_commit();
    load_stage(1, 1); cp_commit();

    for (int kt = 0; kt < KT; kt++) {
        const int st = kt % STG;
        cp_wait1();
        __syncthreads();
        if (kt + 2 < KT) load_stage(kt + 2, (kt + 2) % STG);
        cp_commit();

        uint32_t baseA = (uint32_t)__cvta_generic_to_shared(sA + st * BM * 64);
        uint32_t baseB = (uint32_t)__cvta_generic_to_shared(sB + st * 64 * BN);

#pragma unroll
        for (int kk = 0; kk < 4; kk++) {
            uint32_t a[MF][4];
#pragma unroll
            for (int i = 0; i < MF; i++) {
                int row = wm + i * 16 + (l & 15);
                int g   = kk * 2 + (l >> 4);
                ldmx4(a[i], baseA + (uint32_t)(row * 64 + ((g ^ (row & 7)) << 3)) * 2);
            }
            uint32_t b[NF / 2][4];
#pragma unroll
            for (int j = 0; j < NF / 2; j++) {
                int k = kk * 16 + (l & 15);
                int g = ((wn + j * 16) >> 3) + (l >> 4);
                int gg = (g & 7) ^ (k & 7);
                ldmx4t(b[j], baseB + (uint32_t)(k * BN + (gg << 3)) * 2);
            }
#pragma unroll
            for (int i = 0; i < MF; i++)
#pragma unroll
                for (int j = 0; j < NF / 2; j++) {
                    mma16816(acc[i][2 * j],     a[i], b[j]);
                    mma16816(acc[i][2 * j + 1], a[i], b[j] + 2);
                }
        }
    }

    const int r  = l >> 2;
    const int c0 = (l & 3) * 2;
#pragma unroll
    for (int i = 0; i < MF; i++) {
        int m0 = bm + wm + i * 16;
#pragma unroll
        for (int j = 0; j < NF; j++) {
            int col = bn + wn + j * 8 + c0;
#pragma unroll
            for (int h = 0; h < 2; h++) {
                int m = m0 + r + h * 8;
                float2 val = make_float2(acc[i][j][2 * h], acc[i][j][2 * h + 1]);
                if (MODE == 0) {
                    *reinterpret_cast<float2*>(&C[(size_t)m * N + col]) = val;
                } else {
                    float2 bb = *reinterpret_cast<const float2*>(&bias[col]);
                    val.x += bb.x; val.y += bb.y;
                    int t = m >> 6, b0 = m & 63;
                    *reinterpret_cast<float2*>(
                        &C[((size_t)b0 * TT + t) * OUTF + col]) = val;
                }
            }
        }
    }
}

// ---------------- K-concat lateral GEMM (unchanged champion) ------------------
__global__ __launch_bounds__(128, 4) void latcat_kernel(
    const __half* __restrict__ A1, const __half* __restrict__ A2,
    const __half* __restrict__ Bm, float* __restrict__ C)
{
    constexpr int BM = 64, BN = 64, THREADS = 128;
    constexpr int MF = 2, NF = 4;

    extern __shared__ __half smem[];
    __half* sA = smem;
    __half* sB = smem + STG * BM * 64;

    const int tid  = threadIdx.x;
    const int l    = tid & 31;
    const int warp = tid >> 5;
    const int wm   = (warp >> 1) * 32;
    const int wn   = (warp & 1) * 32;
    const int bm   = blockIdx.y * BM;
    const int bn   = blockIdx.x * BN;

    float acc[MF][NF][4] = {};
    const int KT = KCAT >> 6;   // 24

    auto load_stage = [&](int kt, int st) {
        const int k0 = kt << 6;
#pragma unroll
        for (int i = 0; i < 4; i++) {
            int c = tid + i * THREADS;
            int row = c >> 3, g = c & 7;
            const __half* src = (k0 < HID)
                ? A1 + (size_t)(bm + row) * HID + k0 + (g << 3)
                : A2 + (size_t)(bm + row) * INF + (k0 - HID) + (g << 3);
            cp16(sA + st * BM * 64 + row * 64 + ((g ^ (row & 7)) << 3), src);
        }
#pragma unroll
        for (int i = 0; i < 4; i++) {
            int c = tid + i * THREADS;
            int k = c >> 3, g = c & 7;
            int gg = (g & 7) ^ (k & 7);
            cp16(sB + st * 64 * BN + k * BN + (gg << 3),
                 Bm + (size_t)(k0 + k) * HID + bn + (g << 3));
        }
    };

    load_stage(0, 0); cp_commit();
    load_stage(1, 1); cp_commit();

    for (int kt = 0; kt < KT; kt++) {
        const int st = kt % STG;
        cp_wait1();
        __syncthreads();
        if (kt + 2 < KT) load_stage(kt + 2, (kt + 2) % STG);
        cp_commit();

        uint32_t baseA = (uint32_t)__cvta_generic_to_shared(sA + st * BM * 64);
        uint32_t baseB = (uint32_t)__cvta_generic_to_shared(sB + st * 64 * BN);

#pragma unroll
        for (int kk = 0; kk < 4; kk++) {
            uint32_t a[MF][4];
#pragma unroll
            for (int i = 0; i < MF; i++) {
                int row = wm + i * 16 + (l & 15);
                int g   = kk * 2 + (l >> 4);
                ldmx4(a[i], baseA + (uint32_t)(row * 64 + ((g ^ (row & 7)) << 3)) * 2);
            }
            uint32_t b[NF / 2][4];
#pragma unroll
            for (int j = 0; j < NF / 2; j++) {
                int k = kk * 16 + (l & 15);
                int g = ((wn + j * 16) >> 3) + (l >> 4);
                int gg = (g & 7) ^ (k & 7);
                ldmx4t(b[j], baseB + (uint32_t)(k * BN + (gg << 3)) * 2);
            }
#pragma unroll
            for (int i = 0; i < MF; i++)
#pragma unroll
                for (int j = 0; j < NF / 2; j++) {
                    mma16816(acc[i][2 * j],     a[i], b[j]);
                    mma16816(acc[i][2 * j + 1], a[i], b[j] + 2);
                }
        }
    }

    const int r  = l >> 2;
    const int c0 = (l & 3) * 2;
#pragma unroll
    for (int i = 0; i < MF; i++) {
        int m0 = bm + wm + i * 16;
#pragma unroll
        for (int j = 0; j < NF; j++) {
            int col = bn + wn + j * 8 + c0;
#pragma unroll
            for (int h = 0; h < 2; h++) {
                int m = m0 + r + h * 8;
                *reinterpret_cast<float2*>(&C[(size_t)m * HID + col]) =
                    make_float2(acc[i][j][2 * h], acc[i][j][2 * h + 1]);
            }
        }
    }
}

// ---------------- fused prep: convx | f2h(Wlat) | f2h(Win) | transp(Wout) -----
#define NPA (BB * TT * INF / 4 / 256)   // 6400
#define NPB (HID * HID / 4 / 256)       // 1024
#define NPC (INF * HID / 4 / 256)       // 512
#define NPD ((OUTF / 32) * (HID / 32))  // 512

__global__ __launch_bounds__(256) void prep_kernel(
    const float* __restrict__ x, __half* __restrict__ xh,
    const float* __restrict__ W_lat, const float* __restrict__ W_in,
    __half* __restrict__ Wcat,
    const float* __restrict__ W_out, __half* __restrict__ WoutT)
{
    __shared__ float tile[32][33];
    const int bid = blockIdx.x;
    const int tid = threadIdx.x;

    if (bid < NPA) {                       // convx: permute + fp16
        int i  = bid * 256 + tid;
        int i4 = i % (INF / 4);
        int bt = i / (INF / 4);
        int b = bt / TT, t = bt % TT;
        float4 v = reinterpret_cast<const float4*>(x)[i];
        int dst = (t * BB + b) * (INF / 4) + i4;
        reinterpret_cast<__half2*>(xh)[2 * dst + 0] = __floats2half2_rn(v.x, v.y);
        reinterpret_cast<__half2*>(xh)[2 * dst + 1] = __floats2half2_rn(v.z, v.w);
    } else if (bid < NPA + NPB) {          // f2h W_lat -> Wcat rows 0..1023
        int i = (bid - NPA) * 256 + tid;
        float4 v = reinterpret_cast<const float4*>(W_lat)[i];
        reinterpret_cast<__half2*>(Wcat)[2 * i + 0] = __floats2half2_rn(v.x, v.y);
        reinterpret_cast<__half2*>(Wcat)[2 * i + 1] = __floats2half2_rn(v.z, v.w);
    } else if (bid < NPA + NPB + NPC) {    // f2h W_in -> Wcat rows 1024..1535
        int i = (bid - NPA - NPB) * 256 + tid;
        __half* dst = Wcat + (size_t)HID * HID;
        float4 v = reinterpret_cast<const float4*>(W_in)[i];
        reinterpret_cast<__half2*>(dst)[2 * i + 0] = __floats2half2_rn(v.x, v.y);
        reinterpret_cast<__half2*>(dst)[2 * i + 1] = __floats2half2_rn(v.z, v.w);
    } else {                               // transp W_out -> WoutT
        int e  = bid - NPA - NPB - NPC;
        int ox = (e & 15) * 32;            // 16 tiles along OUT
        int hy = (e >> 4) * 32;            // 32 tiles along HID
        int tx = tid & 31, ty = tid >> 5;  // 32 x 8
#pragma unroll
        for (int rr = 0; rr < 32; rr += 8)
            tile[ty + rr][tx] = W_out[(size_t)(ox + ty + rr) * HID + hy + tx];
        __syncthreads();
#pragma unroll
        for (int rr = 0; rr < 32; rr += 8)
            WoutT[(size_t)(hy + ty + rr) * OUTF + ox + tx] =
                __float2half(tile[tx][ty + rr]);
    }
}

// ---------------- elementwise 20-step scan (exact champion) -------------------
__global__ __launch_bounds__(256) void scan_kernel(
    const float* __restrict__ syn_all,
    const float* __restrict__ trans_k_m,
    const float* __restrict__ trans_asc_k,
    const float* __restrict__ asc_amp,
    const float* __restrict__ trans_asc_r,
    const float* __restrict__ thresh,
    __half* __restrict__ firing,
    float* __restrict__ volt_st, float* __restrict__ asc_st,
    float* __restrict__ fire_st, int t0)
{
    int idx = blockIdx.x * blockDim.x + threadIdx.x;
    int h = idx & (HID - 1);

    float syn[DELAYS];
#pragma unroll
    for (int s = 0; s < DELAYS; s++)
        syn[s] = syn_all[(size_t)(t0 + s) * BH + idx];

    float km  = sigm(trans_k_m[h]);
    float c1  = 0.1f * km;
    float c2  = 1.0f - km;
    float ka0 = sigm(trans_asc_k[h]);
    float ka1 = sigm(trans_asc_k[HID + h]);
    float amp0 = asc_amp[h],       amp1 = asc_amp[HID + h];
    float r0 = 1.0f - 2.0f * sigm(trans_asc_r[h]);
    float r1 = 1.0f - 2.0f * sigm(trans_asc_r[HID + h]);
    float th = thresh[h];

    float f, v, a0, a1;
    if (t0 == 0) {
        f = 0.f; v = 0.f; a0 = 0.f; a1 = 0.f;
    } else {
        f  = fire_st[idx];
        v  = volt_st[idx];
        a0 = asc_st[idx];
        a1 = asc_st[BH + idx];
    }

#pragma unroll
    for (int s = 0; s < DELAYS; s++) {
        a0 = (amp0 + r0 * a0) * f * ka0 + (1.0f - ka0) * a0;
        a1 = (amp1 + r1 * a1) * f * ka1 + (1.0f - ka1) * a1;
        v  = c1 * (syn[s] + a0 + a1) + c2 * v;
        f  = sigm(v - th);
        firing[(size_t)(t0 + s) * BH + idx] = __float2half(f);
    }
    fire_st[idx] = f;
    volt_st[idx] = v;
    asc_st[idx] = a0;
    asc_st[BH + idx] = a1;
}

// ---------------- launch (single stream) --------------------------------------
extern "C" void kernel_launch(void* const* d_in, const int* in_sizes, int n_in,
                              void* d_out, int out_size)
{
    const float* x           = (const float*)d_in[0];
    const float* W_in        = (const float*)d_in[1];
    const float* W_lat       = (const float*)d_in[2];
    const float* thresh      = (const float*)d_in[3];
    const float* trans_k_m   = (const float*)d_in[4];
    const float* trans_asc_k = (const float*)d_in[5];
    const float* asc_amp     = (const float*)d_in[6];
    const float* trans_asc_r = (const float*)d_in[7];
    const float* W_out       = (const float*)d_in[8];
    const float* b_out       = (const float*)d_in[9];
    float* out = (float*)d_out;

    __half *xh, *Wcat, *WoutT, *firing;
    float *syn, *volt, *asc, *fire;
    cudaGetSymbolAddress((void**)&xh,     g_xh);
    cudaGetSymbolAddress((void**)&Wcat,   g_Wcat);
    cudaGetSymbolAddress((void**)&WoutT,  g_WoutT);
    cudaGetSymbolAddress((void**)&syn,    g_syn);
    cudaGetSymbolAddress((void**)&firing, g_firing);
    cudaGetSymbolAddress((void**)&volt,   g_volt);
    cudaGetSymbolAddress((void**)&asc,    g_asc);
    cudaGetSymbolAddress((void**)&fire,   g_fire);

    const int SM_LAT = STG * (64 * 64 + 64 * 64) * 2;     // 49152
    cudaFuncSetAttribute(mgemm64<0>,
                         cudaFuncAttributeMaxDynamicSharedMemorySize, SM_LAT);
    cudaFuncSetAttribute(mgemm64<2>,
                         cudaFuncAttributeMaxDynamicSharedMemorySize, SM_LAT);
    cudaFuncSetAttribute(latcat_kernel,
                         cudaFuncAttributeMaxDynamicSharedMemorySize, SM_LAT);

    // ---- fused prep: all conversions in one launch ----
    prep_kernel<<<NPA + NPB + NPC + NPD, 256>>>(
        x, xh, W_lat, W_in, Wcat, W_out, WoutT);

    // ---- block 0 input projection (64x64 tiles, 320 CTAs) ----
    mgemm64<0><<<dim3(HID / 64, MBLK / 64), 128, SM_LAT>>>(
        xh, Wcat + (size_t)HID * HID, syn, nullptr, MBLK, HID, INF, INF);

    // ---- recurrent chain: K-concat lateral + scan ----
    for (int blk = 0; blk < NBLK; blk++) {
        if (blk > 0) {
            latcat_kernel<<<dim3(HID / 64, MBLK / 64), 128, SM_LAT>>>(
                firing + (size_t)(blk - 1) * MBLK * HID,
                xh + (size_t)blk * MBLK * INF,
                Wcat,
                syn + (size_t)blk * MBLK * HID);
        }
        scan_kernel<<<BH / 256, 256>>>(
            syn, trans_k_m, trans_asc_k, asc_amp, trans_asc_r, thresh,
            firing, volt, asc, fire, blk * DELAYS);
    }

    // ---- readout (64x64 tiles, 1600 CTAs, fused bias + permute) ----
    mgemm64<2><<<dim3(OUTF / 64, (BB * TT) / 64), 128, SM_LAT>>>(
        firing, WoutT, out, b_out, BB * TT, OUTF, HID, HID);
}